// round 15
// baseline (speedup 1.0000x reference)
#include <cuda_runtime.h>
#include <cuda_bf16.h>
#include <cstdint>
#include <stdint.h>
#include <math.h>

#define EPSF 1e-6f

// ---------------- scratch (device globals; no allocation allowed) ----------
__device__ float g_raw1[1536 * 1536];      // x @ qkv1_w   [B*N, 3*D]
__device__ float g_raw2[1536 * 1536];      // x @ qkv2_w
__device__ float g_kT1[16 * 64 * 768];     // k1 transposed per head: [bh][dk][n]
__device__ float g_kT2[16 * 64 * 768];
__device__ float g_S1[16 * 768 * 768];
__device__ float g_S2[16 * 768 * 768];
__device__ float g_A1[16 * 768 * 768];
__device__ float g_A2[16 * 768 * 768];
__device__ float g_Cr[16 * 768 * 768];     // log(A1@A2 + eps)
__device__ float g_Cl[16 * 768 * 768];     // log(A2@A1 + eps)
__device__ float g_Smix[16 * 768 * 768];   // Smix, then softmax(Smix) in place
__device__ float g_trans[16 * 768 * 64];   // A2 @ v2
__device__ float g_y[1536 * 512];          // y_base + w*y_chain, [B*N, D]
// bf16 copies for the HMMA path
__device__ __nv_bfloat16 g_A1b[16 * 768 * 768];
__device__ __nv_bfloat16 g_A2b[16 * 768 * 768];
__device__ __nv_bfloat16 g_A1tb[16 * 768 * 768];   // A1^T per head
__device__ __nv_bfloat16 g_A2tb[16 * 768 * 768];   // A2^T per head

// ============================ helpers =======================================
__device__ __forceinline__ uint32_t smem_u32(const void* p) {
    uint32_t a;
    asm("{ .reg .u64 t; cvta.to.shared.u64 t, %1; cvt.u32.u64 %0, t; }"
        : "=r"(a) : "l"(p));
    return a;
}
__device__ __forceinline__ float tanh_apx(float x) {
    float y;
    asm("tanh.approx.f32 %0, %1;" : "=f"(y) : "f"(x));
    return y;
}
__device__ __forceinline__ float sigmoid_f(float x) {
    return 0.5f * tanh_apx(0.5f * x) + 0.5f;
}

#define LDSM4(r, addr) \
    asm volatile("ldmatrix.sync.aligned.m8n8.x4.shared.b16 {%0,%1,%2,%3}, [%4];" \
        : "=r"((r)[0]), "=r"((r)[1]), "=r"((r)[2]), "=r"((r)[3]) : "r"(addr))
#define MMA_BF16(d, a, b) \
    asm volatile("mma.sync.aligned.m16n8k16.row.col.f32.bf16.bf16.f32 " \
        "{%0,%1,%2,%3}, {%4,%5,%6,%7}, {%8,%9}, {%0,%1,%2,%3};" \
        : "+f"((d)[0]), "+f"((d)[1]), "+f"((d)[2]), "+f"((d)[3]) \
        : "r"((a)[0]), "r"((a)[1]), "r"((a)[2]), "r"((a)[3]), \
          "r"((b)[0]), "r"((b)[1]))
#define CP16(dst, src) \
    asm volatile("cp.async.cg.shared.global [%0], [%1], 16;" \
        :: "r"(dst), "l"(src))
#define CP_COMMIT() asm volatile("cp.async.commit_group;" ::: "memory")
#define CP_WAIT2()  asm volatile("cp.async.wait_group 2;" ::: "memory")

// ---------------------------------------------------------------------------
// HMMA bf16 GEMM with fused log epilogue, merged Cr/Cl:
//   z < 16 : Cr[z] = log(A1b[z] @ A2tb[z]^T + eps)
//   z >= 16: Cl[z-16] = log(A2b[] @ A1tb[]^T + eps)
// CTA 128x128, 8 warps, warp tile 64x32, K-chunk 32.
// 4-stage cp.async pipeline (dynamic smem 80KB), rows padded to 40 bf16.
// ---------------------------------------------------------------------------
#define SPAD 40
#define STG_B 20480          // per-stage bytes: A (10240) + B (10240)
#define HSM_TOTAL (4 * STG_B)

__global__ __launch_bounds__(256) void hmma_logC(
    const __nv_bfloat16* __restrict__ A1b, const __nv_bfloat16* __restrict__ A2tb,
    const __nv_bfloat16* __restrict__ A2b, const __nv_bfloat16* __restrict__ A1tb,
    float* __restrict__ Cr, float* __restrict__ Cl)
{
    extern __shared__ __align__(16) char dsm[];
    const uint32_t sb = smem_u32(dsm);

    const int tid = threadIdx.x;
    const int wid = tid >> 5, lane = tid & 31;
    const int wm = (wid & 1) * 64;
    const int wn = (wid >> 1) * 32;

    const size_t HB = 768 * 768;
    const int zz = blockIdx.z;
    const __nv_bfloat16 *Ab, *Bb;
    float* Cp;
    if (zz < 16) {
        Ab = A1b + (size_t)zz * HB; Bb = A2tb + (size_t)zz * HB; Cp = g_Cr ? Cr + (size_t)zz * HB : nullptr;
    } else {
        const int z = zz - 16;
        Ab = A2b + (size_t)z * HB; Bb = A1tb + (size_t)z * HB; Cp = Cl + (size_t)z * HB;
    }
    const __nv_bfloat16* Ag = Ab + (size_t)blockIdx.y * 128 * 768;
    const __nv_bfloat16* Bg = Bb + (size_t)blockIdx.x * 128 * 768;
    float* Cg = Cp + (size_t)blockIdx.y * 128 * 768 + blockIdx.x * 128;

    // ldmatrix lane address components
    const int rA = (lane & 7) + ((lane >> 3) & 1) * 8;
    const int cA = (lane >> 4) * 8;
    const int rB16 = lane & 15;
    const int cB = (lane >> 4) * 8;

    // global/smem copy mapping: 2 x 16B per tile per thread
    const int gr0 = tid >> 2, gc0 = (tid & 3) * 8;
    const int gr1 = gr0 + 64;
    const uint32_t dA0 = (uint32_t)(gr0 * SPAD + gc0) * 2;
    const uint32_t dA1 = (uint32_t)(gr1 * SPAD + gc0) * 2;

    float acc[16][4];
#pragma unroll
    for (int i = 0; i < 16; i++)
#pragma unroll
        for (int j = 0; j < 4; j++) acc[i][j] = 0.f;

    // prologue: prefetch kb = 0, 1, 2 into stages 0, 1, 2
#pragma unroll
    for (int p = 0; p < 3; p++) {
        const __nv_bfloat16* Ak = Ag + p * 32 + gc0;
        const __nv_bfloat16* Bk = Bg + p * 32 + gc0;
        const uint32_t st = sb + p * STG_B;
        CP16(st + dA0, Ak + (size_t)gr0 * 768);
        CP16(st + dA1, Ak + (size_t)gr1 * 768);
        CP16(st + 10240 + dA0, Bk + (size_t)gr0 * 768);
        CP16(st + 10240 + dA1, Bk + (size_t)gr1 * 768);
        CP_COMMIT();
    }

    for (int kb = 0; kb < 24; kb++) {
        const int cur = kb & 3;
        CP_WAIT2();                    // group kb complete (kb+1, kb+2 outstanding)
        __syncthreads();
        if (kb + 3 < 24) {
            const int nxt = (kb + 3) & 3;
            const __nv_bfloat16* Ak = Ag + (kb + 3) * 32 + gc0;
            const __nv_bfloat16* Bk = Bg + (kb + 3) * 32 + gc0;
            const uint32_t st = sb + nxt * STG_B;
            CP16(st + dA0, Ak + (size_t)gr0 * 768);
            CP16(st + dA1, Ak + (size_t)gr1 * 768);
            CP16(st + 10240 + dA0, Bk + (size_t)gr0 * 768);
            CP16(st + 10240 + dA1, Bk + (size_t)gr1 * 768);
        }
        CP_COMMIT();                   // always commit (possibly empty group)

        const uint32_t bA = sb + cur * STG_B;
        const uint32_t bB = bA + 10240;
#pragma unroll
        for (int ks = 0; ks < 2; ks++) {
            const int kbase = ks * 16;
            uint32_t af[4][4], bf[4][2];
#pragma unroll
            for (int mi = 0; mi < 4; mi++) {
                uint32_t ad = bA + (uint32_t)((wm + mi * 16 + rA) * SPAD + kbase + cA) * 2;
                LDSM4(af[mi], ad);
            }
#pragma unroll
            for (int p = 0; p < 2; p++) {
                uint32_t r[4];
                uint32_t bd = bB + (uint32_t)((wn + p * 16 + rB16) * SPAD + kbase + cB) * 2;
                LDSM4(r, bd);
                bf[p * 2 + 0][0] = r[0]; bf[p * 2 + 0][1] = r[2];
                bf[p * 2 + 1][0] = r[1]; bf[p * 2 + 1][1] = r[3];
            }
#pragma unroll
            for (int mi = 0; mi < 4; mi++)
#pragma unroll
                for (int ni = 0; ni < 4; ni++)
                    MMA_BF16(acc[mi * 4 + ni], af[mi], bf[ni]);
        }
    }

    // epilogue
    const int g = lane >> 2, t2 = (lane & 3) * 2;
#pragma unroll
    for (int mi = 0; mi < 4; mi++) {
#pragma unroll
        for (int ni = 0; ni < 4; ni++) {
            const float* d = acc[mi * 4 + ni];
            const int col = wn + ni * 8 + t2;
            float2 v0, v1;
            v0.x = __logf(d[0] + EPSF); v0.y = __logf(d[1] + EPSF);
            v1.x = __logf(d[2] + EPSF); v1.y = __logf(d[3] + EPSF);
            *(float2*)(Cg + (size_t)(wm + mi * 16 + g) * 768 + col)     = v0;
            *(float2*)(Cg + (size_t)(wm + mi * 16 + g + 8) * 768 + col) = v1;
        }
    }
}

// ---------------------------------------------------------------------------
// Generic 128x128x8 register-tiled SGEMM (row-major A[M,K], B[K,N], C[M,N]).
// ---------------------------------------------------------------------------
__global__ __launch_bounds__(256) void sgemm128(
    const float* __restrict__ A, int lda, size_t sAb, size_t sAh,
    const float* __restrict__ B, int ldb, size_t sBb, size_t sBh,
    float* __restrict__ C, int ldc, size_t sCb, size_t sCh,
    int K, float alpha)
{
    const size_t ob = blockIdx.z >> 3, oh = blockIdx.z & 7;
    A += ob * sAb + oh * sAh + (size_t)blockIdx.y * 128 * lda;
    B += ob * sBb + oh * sBh + blockIdx.x * 128;
    C += ob * sCb + oh * sCh + (size_t)blockIdx.y * 128 * ldc + blockIdx.x * 128;

    __shared__ float As[8][128];
    __shared__ float Bs[8][128];

    const int tid  = threadIdx.x;
    const int aRow = tid >> 1, aCol = (tid & 1) * 4;
    const int bRow = tid >> 5, bCol = (tid & 31) * 4;
    const int tx = (tid & 15) * 8, ty = (tid >> 4) * 8;

    float acc[8][8];
#pragma unroll
    for (int i = 0; i < 8; i++)
#pragma unroll
        for (int j = 0; j < 8; j++) acc[i][j] = 0.f;

    for (int k0 = 0; k0 < K; k0 += 8) {
        float4 av = *(const float4*)(A + (size_t)aRow * lda + k0 + aCol);
        As[aCol + 0][aRow] = av.x; As[aCol + 1][aRow] = av.y;
        As[aCol + 2][aRow] = av.z; As[aCol + 3][aRow] = av.w;
        *(float4*)&Bs[bRow][bCol] =
            *(const float4*)(B + (size_t)(k0 + bRow) * ldb + bCol);
        __syncthreads();
#pragma unroll
        for (int k = 0; k < 8; ++k) {
            float4 a0 = *(float4*)&As[k][ty];
            float4 a1 = *(float4*)&As[k][ty + 4];
            float4 b0 = *(float4*)&Bs[k][tx];
            float4 b1 = *(float4*)&Bs[k][tx + 4];
            float ar[8] = {a0.x, a0.y, a0.z, a0.w, a1.x, a1.y, a1.z, a1.w};
            float br[8] = {b0.x, b0.y, b0.z, b0.w, b1.x, b1.y, b1.z, b1.w};
#pragma unroll
            for (int i = 0; i < 8; i++)
#pragma unroll
                for (int j = 0; j < 8; j++)
                    acc[i][j] = fmaf(ar[i], br[j], acc[i][j]);
        }
        __syncthreads();
    }

#pragma unroll
    for (int i = 0; i < 8; i++) {
        *(float4*)&C[(size_t)(ty + i) * ldc + tx] =
            make_float4(alpha * acc[i][0], alpha * acc[i][1],
                        alpha * acc[i][2], alpha * acc[i][3]);
        *(float4*)&C[(size_t)(ty + i) * ldc + tx + 4] =
            make_float4(alpha * acc[i][4], alpha * acc[i][5],
                        alpha * acc[i][6], alpha * acc[i][7]);
    }
}

// ---------------------------------------------------------------------------
// 64x64x16 SGEMM (row-major). AV products + output projection.
// ---------------------------------------------------------------------------
__global__ __launch_bounds__(256) void sgemm64(
    const float* __restrict__ A, int lda, size_t sAb, size_t sAh,
    const float* __restrict__ B, int ldb, size_t sBb, size_t sBh,
    float* __restrict__ C, int ldc, size_t sCb, size_t sCh,
    int K, int accumulate, const float* __restrict__ alphaPtr)
{
    const size_t ob = blockIdx.z >> 3, oh = blockIdx.z & 7;
    A += ob * sAb + oh * sAh + (size_t)blockIdx.y * 64 * lda;
    B += ob * sBb + oh * sBh + blockIdx.x * 64;
    C += ob * sCb + oh * sCh + (size_t)blockIdx.y * 64 * ldc + blockIdx.x * 64;

    float alpha = 1.0f;
    if (alphaPtr) alpha = sigmoid_f(alphaPtr[0]);

    __shared__ float As[16][64];
    __shared__ float Bs[16][64];

    const int tid = threadIdx.x;
    const int tx = (tid & 15) * 4, ty = (tid >> 4) * 4;
    const int ar = tid >> 2, ac = (tid & 3) * 4;
    const int br = tid >> 4, bc = (tid & 15) * 4;

    float acc[4][4];
#pragma unroll
    for (int i = 0; i < 4; i++)
#pragma unroll
        for (int j = 0; j < 4; j++) acc[i][j] = 0.f;

    for (int k0 = 0; k0 < K; k0 += 16) {
        float4 av = *(const float4*)(A + (size_t)ar * lda + k0 + ac);
        As[ac + 0][ar] = av.x; As[ac + 1][ar] = av.y;
        As[ac + 2][ar] = av.z; As[ac + 3][ar] = av.w;
        *(float4*)&Bs[br][bc] =
            *(const float4*)(B + (size_t)(k0 + br) * ldb + bc);
        __syncthreads();
#pragma unroll
        for (int k = 0; k < 16; k++) {
            float4 a = *(float4*)&As[k][ty];
            float4 b = *(float4*)&Bs[k][tx];
            float ar4[4] = {a.x, a.y, a.z, a.w};
            float br4[4] = {b.x, b.y, b.z, b.w};
#pragma unroll
            for (int i = 0; i < 4; i++)
#pragma unroll
                for (int j = 0; j < 4; j++)
                    acc[i][j] = fmaf(ar4[i], br4[j], acc[i][j]);
        }
        __syncthreads();
    }

#pragma unroll
    for (int i = 0; i < 4; i++) {
        float* cp = &C[(size_t)(ty + i) * ldc + tx];
        float4 v = make_float4(alpha * acc[i][0], alpha * acc[i][1],
                               alpha * acc[i][2], alpha * acc[i][3]);
        if (accumulate) {
            float4 o = *(float4*)cp;
            v.x += o.x; v.y += o.y; v.z += o.z; v.w += o.w;
        }
        *(float4*)cp = v;
    }
}

// ---------------------------------------------------------------------------
// Transpose the per-head K slice of the fused QKV buffer into [bh][dk][n].
// ---------------------------------------------------------------------------
__global__ void transposeK(const float* __restrict__ raw, float* __restrict__ kT)
{
    __shared__ float tile[32][33];
    const int bh = blockIdx.z, b = bh >> 3, h = bh & 7;
    const int n0 = blockIdx.x * 32, d0 = blockIdx.y * 32;
    const float* src = raw + (size_t)b * 768 * 1536 + 512 + h * 64;
#pragma unroll
    for (int i = 0; i < 4; i++) {
        int n = n0 + threadIdx.y + i * 8;
        tile[threadIdx.y + i * 8][threadIdx.x] =
            src[(size_t)n * 1536 + d0 + threadIdx.x];
    }
    __syncthreads();
    float* dst = kT + (size_t)bh * 64 * 768;
#pragma unroll
    for (int i = 0; i < 4; i++) {
        int d = d0 + threadIdx.y + i * 8;
        dst[(size_t)d * 768 + n0 + threadIdx.x] = tile[threadIdx.x][threadIdx.y + i * 8];
    }
}

// ---------------------------------------------------------------------------
// Transpose + bf16-convert; merged pair: z<16 -> (in1,out1), else (in2,out2).
// ---------------------------------------------------------------------------
__global__ void transpose_cvt(const float* __restrict__ in1,
                              __nv_bfloat16* __restrict__ out1,
                              const float* __restrict__ in2,
                              __nv_bfloat16* __restrict__ out2)
{
    __shared__ float t[32][33];
    const int zz = blockIdx.z;
    const float* in = (zz < 16) ? in1 : in2;
    __nv_bfloat16* out = (zz < 16) ? out1 : out2;
    const size_t base = (size_t)(zz & 15) * 768 * 768;
    const int x0 = blockIdx.x * 32, y0 = blockIdx.y * 32;
#pragma unroll
    for (int i = 0; i < 4; i++)
        t[threadIdx.y + i * 8][threadIdx.x] =
            in[base + (size_t)(y0 + threadIdx.y + i * 8) * 768 + x0 + threadIdx.x];
    __syncthreads();
#pragma unroll
    for (int i = 0; i < 4; i++)
        out[base + (size_t)(x0 + threadIdx.y + i * 8) * 768 + y0 + threadIdx.x] =
            __float2bfloat16_rn(t[threadIdx.x][threadIdx.y + i * 8]);
}

// ---------------------------------------------------------------------------
// Row softmax, 768 cols; merged pair (second pair optional).
// ---------------------------------------------------------------------------
__global__ __launch_bounds__(256) void softmax768(
    const float* __restrict__ in1, float* __restrict__ out1,
    __nv_bfloat16* __restrict__ outb1,
    const float* __restrict__ in2, float* __restrict__ out2,
    __nv_bfloat16* __restrict__ outb2)
{
    size_t row = blockIdx.x;
    const float* in = in1; float* out = out1; __nv_bfloat16* outb = outb1;
    if (row >= 12288) { row -= 12288; in = in2; out = out2; outb = outb2; }
    const float* p = in + row * 768;
    const int t = threadIdx.x;
    float v0 = p[t], v1 = p[t + 256], v2 = p[t + 512];

    __shared__ float red[256];
    red[t] = fmaxf(fmaxf(v0, v1), v2);
    __syncthreads();
#pragma unroll
    for (int s = 128; s > 0; s >>= 1) {
        if (t < s) red[t] = fmaxf(red[t], red[t + s]);
        __syncthreads();
    }
    const float m = red[0];
    __syncthreads();

    float e0 = __expf(v0 - m), e1 = __expf(v1 - m), e2 = __expf(v2 - m);
    red[t] = e0 + e1 + e2;
    __syncthreads();
#pragma unroll
    for (int s = 128; s > 0; s >>= 1) {
        if (t < s) red[t] += red[t + s];
        __syncthreads();
    }
    const float inv = 1.0f / red[0];
    e0 *= inv; e1 *= inv; e2 *= inv;
    float* q = out + row * 768;
    q[t] = e0; q[t + 256] = e1; q[t + 512] = e2;
    if (outb) {
        __nv_bfloat16* qb = outb + row * 768;
        qb[t] = __float2bfloat16_rn(e0);
        qb[t + 256] = __float2bfloat16_rn(e1);
        qb[t + 512] = __float2bfloat16_rn(e2);
    }
}

// ---------------------------------------------------------------------------
// Fused gate conv + Smix (fast-math MUFU version).
// ---------------------------------------------------------------------------
__global__ __launch_bounds__(256) void mix_kernel(
    const float* __restrict__ S1, const float* __restrict__ S2,
    const float* __restrict__ Cr, const float* __restrict__ Cl,
    float* __restrict__ Smix,
    const float* __restrict__ w1, const float* __restrict__ b1,
    const float* __restrict__ w2, const float* __restrict__ b2)
{
    __shared__ float T1[64][65];
    __shared__ float T2[64][65];
    __shared__ float sw1[96], sb1[16], sw2[64], sb2[4];

    const int tid = threadIdx.x;
    if (tid < 96) sw1[tid] = w1[tid];
    if (tid < 16) sb1[tid] = b1[tid];
    if (tid < 64) sw2[tid] = w2[tid];
    if (tid < 4)  sb2[tid] = b2[tid];

    const size_t base = (size_t)blockIdx.z * 768 * 768;
    const int nt = blockIdx.y * 64, mt = blockIdx.x * 64;

#pragma unroll
    for (int u = 0; u < 4; u++) {
        int f = tid + u * 256;
        int r = f >> 4, c4 = (f & 15) * 4;
        size_t off = base + (size_t)(mt + r) * 768 + nt + c4;
        float4 a = *(const float4*)(S1 + off);
        T1[c4 + 0][r] = a.x; T1[c4 + 1][r] = a.y; T1[c4 + 2][r] = a.z; T1[c4 + 3][r] = a.w;
        float4 c = *(const float4*)(S2 + off);
        T2[c4 + 0][r] = c.x; T2[c4 + 1][r] = c.y; T2[c4 + 2][r] = c.z; T2[c4 + 3][r] = c.w;
    }
    __syncthreads();

#pragma unroll 1
    for (int u = 0; u < 16; u++) {
        int e = tid + u * 256;
        int i = e >> 6, j = e & 63;
        size_t idx = base + (size_t)(nt + i) * 768 + mt + j;
        float s1 = S1[idx], s2 = S2[idx];
        float s1t = T1[i][j], s2t = T2[i][j];
        float cr = Cr[idx], cl = Cl[idx];
        float feat[6] = {s1, s2, s1t, s2t, cr, cl};

        float g[4] = {sb2[0], sb2[1], sb2[2], sb2[3]};
#pragma unroll
        for (int o = 0; o < 16; o++) {
            float hv = sb1[o];
#pragma unroll
            for (int c = 0; c < 6; c++) hv = fmaf(feat[c], sw1[o * 6 + c], hv);
            float th = tanh_apx(0.7978845608028654f * (hv + 0.044715f * hv * hv * hv));
            float hid = 0.5f * hv * (1.0f + th);
#pragma unroll
            for (int q = 0; q < 4; q++) g[q] = fmaf(hid, sw2[q * 16 + o], g[q]);
        }
        float gA = sigmoid_f(g[0]);
        float gO = sigmoid_f(g[1]);
        float gN = sigmoid_f(g[2]);
        float gC = sigmoid_f(g[3]);
        float mx = fmaxf(s1, s2), mn = fminf(s1, s2);
        float lae = mx + __logf(1.0f + __expf(mn - mx));
        Smix[idx] = s1 + gA * s2 + gO * (lae - s1) - gN * (0.5f * s2) + gC * cr;
    }
}

// ---------------------------------------------------------------------------
extern "C" void kernel_launch(void* const* d_in, const int* in_sizes, int n_in,
                              void* d_out, int out_size)
{
    const float* x        = (const float*)d_in[0];
    const float* qkv1_w   = (const float*)d_in[1];
    const float* qkv2_w   = (const float*)d_in[2];
    const float* proj_w   = (const float*)d_in[3];
    const float* conv1_w  = (const float*)d_in[4];
    const float* conv1_b  = (const float*)d_in[5];
    const float* conv2_w  = (const float*)d_in[6];
    const float* conv2_b  = (const float*)d_in[7];
    const float* chlogit  = (const float*)d_in[8];
    float* out = (float*)d_out;

    float *p_raw1, *p_raw2, *p_kT1, *p_kT2, *p_S1, *p_S2, *p_A1, *p_A2;
    float *p_Cr, *p_Cl, *p_Smix, *p_trans, *p_y;
    __nv_bfloat16 *p_A1b, *p_A2b, *p_A1tb, *p_A2tb;
    cudaGetSymbolAddress((void**)&p_raw1, g_raw1);
    cudaGetSymbolAddress((void**)&p_raw2, g_raw2);
    cudaGetSymbolAddress((void**)&p_kT1, g_kT1);
    cudaGetSymbolAddress((void**)&p_kT2, g_kT2);
    cudaGetSymbolAddress((void**)&p_S1, g_S1);
    cudaGetSymbolAddress((void**)&p_S2, g_S2);
    cudaGetSymbolAddress((void**)&p_A1, g_A1);
    cudaGetSymbolAddress((void**)&p_A2, g_A2);
    cudaGetSymbolAddress((void**)&p_Cr, g_Cr);
    cudaGetSymbolAddress((void**)&p_Cl, g_Cl);
    cudaGetSymbolAddress((void**)&p_Smix, g_Smix);
    cudaGetSymbolAddress((void**)&p_trans, g_trans);
    cudaGetSymbolAddress((void**)&p_y, g_y);
    cudaGetSymbolAddress((void**)&p_A1b, g_A1b);
    cudaGetSymbolAddress((void**)&p_A2b, g_A2b);
    cudaGetSymbolAddress((void**)&p_A1tb, g_A1tb);
    cudaGetSymbolAddress((void**)&p_A2tb, g_A2tb);

    cudaFuncSetAttribute(hmma_logC,
                         cudaFuncAttributeMaxDynamicSharedMemorySize, HSM_TOTAL);

    const size_t SB = 768 * 768;
    const size_t RB = 768 * 1536;
    const size_t VB = 768 * 64;
    const size_t YB = 768 * 512;

    // 1) fused QKV projections
    sgemm128<<<dim3(12, 12, 1), 256>>>(x, 512, 0, 0, qkv1_w, 1536, 0, 0,
                                       p_raw1, 1536, 0, 0, 512, 1.0f);
    sgemm128<<<dim3(12, 12, 1), 256>>>(x, 512, 0, 0, qkv2_w, 1536, 0, 0,
                                       p_raw2, 1536, 0, 0, 512, 1.0f);

    // 2) transpose K slices
    transposeK<<<dim3(24, 2, 16), dim3(32, 8)>>>(p_raw1, p_kT1);
    transposeK<<<dim3(24, 2, 16), dim3(32, 8)>>>(p_raw2, p_kT2);

    // 3) S = (q @ k^T) / sqrt(DK)
    sgemm128<<<dim3(6, 6, 16), 256>>>(p_raw1, 1536, RB, 64,
                                      p_kT1, 768, 8 * VB, VB,
                                      p_S1, 768, 8 * SB, SB, 64, 0.125f);
    sgemm128<<<dim3(6, 6, 16), 256>>>(p_raw2, 1536, RB, 64,
                                      p_kT2, 768, 8 * VB, VB,
                                      p_S2, 768, 8 * SB, SB, 64, 0.125f);

    // 4) A1/A2 softmax (+ bf16 copies) — merged
    softmax768<<<24576, 256>>>(p_S1, p_A1, p_A1b, p_S2, p_A2, p_A2b);

    // 4b) transposed bf16 copies — merged
    transpose_cvt<<<dim3(24, 24, 32), dim3(32, 8)>>>(p_A1, p_A1tb, p_A2, p_A2tb);

    // 5) Cr & Cl in one launch — HMMA bf16, 4-stage cp.async pipeline
    hmma_logC<<<dim3(6, 6, 32), 256, HSM_TOTAL>>>(p_A1b, p_A2tb, p_A2b, p_A1tb,
                                                  p_Cr, p_Cl);

    // 6) fused gate conv + Smix
    mix_kernel<<<dim3(12, 12, 16), 256>>>(p_S1, p_S2, p_Cr, p_Cl, p_Smix,
                                          conv1_w, conv1_b, conv2_w, conv2_b);

    // 7) A = softmax(Smix) in place
    softmax768<<<12288, 256>>>(p_Smix, p_Smix, nullptr,
                               p_Smix, p_Smix, nullptr);

    // 8) transport = A2 @ v2
    sgemm64<<<dim3(1, 12, 16), 256>>>(p_A2, 768, 8 * SB, SB,
                                      p_raw2 + 1024, 1536, RB, 64,
                                      p_trans, 64, 8 * VB, VB,
                                      768, 0, nullptr);
    // 9) y = A @ v1
    sgemm64<<<dim3(1, 12, 16), 256>>>(p_Smix, 768, 8 * SB, SB,
                                      p_raw1 + 1024, 1536, RB, 64,
                                      p_y, 512, YB, 64,
                                      768, 0, nullptr);
    // 10) y += sigmoid(chain_logit) * (A1 @ transport)
    sgemm64<<<dim3(1, 12, 16), 256>>>(p_A1, 768, 8 * SB, SB,
                                      p_trans, 64, 8 * VB, VB,
                                      p_y, 512, YB, 64,
                                      768, 1, chlogit);

    // 11) out = y @ proj_w
    sgemm64<<<dim3(8, 24, 1), 256>>>(p_y, 512, 0, 0, proj_w, 512, 0, 0,
                                     out, 512, 0, 0, 512, 0, nullptr);
}

// round 16
// speedup vs baseline: 1.2371x; 1.2371x over previous
#include <cuda_runtime.h>
#include <cuda_bf16.h>
#include <cstdint>
#include <stdint.h>
#include <math.h>

#define EPSF 1e-6f

// ---------------- scratch (device globals; no allocation allowed) ----------
__device__ float g_raw1[1536 * 1536];      // x @ qkv1_w   [B*N, 3*D]
__device__ float g_raw2[1536 * 1536];      // x @ qkv2_w
__device__ float g_kT1[16 * 64 * 768];     // k1 transposed per head
__device__ float g_kT2[16 * 64 * 768];
__device__ float g_S1[16 * 768 * 768];
__device__ float g_S2[16 * 768 * 768];
__device__ float g_A1[16 * 768 * 768];     // A1 fp32; later reused as Craw
__device__ float g_A2[16 * 768 * 768];
__device__ float g_Cr[16 * 768 * 768];     // log(A1@A2 + eps)
__device__ float g_Cl[16 * 768 * 768];     // log(A2@A1 + eps)
__device__ float g_Smix[16 * 768 * 768];   // Smix -> softmax in place
__device__ float g_y2[1536 * 512];         // y_chain = Craw @ v2
__device__ float g_y[1536 * 512];          // y_base
// bf16 copies for the HMMA path
__device__ __nv_bfloat16 g_A1b[16 * 768 * 768];
__device__ __nv_bfloat16 g_A2b[16 * 768 * 768];
__device__ __nv_bfloat16 g_A1tb[16 * 768 * 768];
__device__ __nv_bfloat16 g_A2tb[16 * 768 * 768];

// ============================ helpers =======================================
__device__ __forceinline__ uint32_t smem_u32(const void* p) {
    uint32_t a;
    asm("{ .reg .u64 t; cvta.to.shared.u64 t, %1; cvt.u32.u64 %0, t; }"
        : "=r"(a) : "l"(p));
    return a;
}
__device__ __forceinline__ float tanh_apx(float x) {
    float y;
    asm("tanh.approx.f32 %0, %1;" : "=f"(y) : "f"(x));
    return y;
}
__device__ __forceinline__ float sigmoid_f(float x) {
    return 0.5f * tanh_apx(0.5f * x) + 0.5f;
}

#define LDSM4(r, addr) \
    asm volatile("ldmatrix.sync.aligned.m8n8.x4.shared.b16 {%0,%1,%2,%3}, [%4];" \
        : "=r"((r)[0]), "=r"((r)[1]), "=r"((r)[2]), "=r"((r)[3]) : "r"(addr))
#define MMA_BF16(d, a, b) \
    asm volatile("mma.sync.aligned.m16n8k16.row.col.f32.bf16.bf16.f32 " \
        "{%0,%1,%2,%3}, {%4,%5,%6,%7}, {%8,%9}, {%0,%1,%2,%3};" \
        : "+f"((d)[0]), "+f"((d)[1]), "+f"((d)[2]), "+f"((d)[3]) \
        : "r"((a)[0]), "r"((a)[1]), "r"((a)[2]), "r"((a)[3]), \
          "r"((b)[0]), "r"((b)[1]))
#define CP16(dst, src) \
    asm volatile("cp.async.cg.shared.global [%0], [%1], 16;" \
        :: "r"(dst), "l"(src))
#define CP_COMMIT() asm volatile("cp.async.commit_group;" ::: "memory")
#define CP_WAIT2()  asm volatile("cp.async.wait_group 2;" ::: "memory")

// ---------------------------------------------------------------------------
// HMMA bf16 GEMM, merged Cr/Cl, fused log epilogue. For z<16 also stores the
// RAW product (fp32) into Craw — reused later as y_chain = Craw @ v2.
// CTA 128x128, 8 warps, warp tile 64x32, 4-stage cp.async pipeline.
// ---------------------------------------------------------------------------
#define SPAD 40
#define STG_B 20480
#define HSM_TOTAL (4 * STG_B)

__global__ __launch_bounds__(256) void hmma_logC(
    const __nv_bfloat16* __restrict__ A1b, const __nv_bfloat16* __restrict__ A2tb,
    const __nv_bfloat16* __restrict__ A2b, const __nv_bfloat16* __restrict__ A1tb,
    float* __restrict__ Cr, float* __restrict__ Cl, float* __restrict__ Craw)
{
    extern __shared__ __align__(16) char dsm[];
    const uint32_t sb = smem_u32(dsm);

    const int tid = threadIdx.x;
    const int wid = tid >> 5, lane = tid & 31;
    const int wm = (wid & 1) * 64;
    const int wn = (wid >> 1) * 32;

    const size_t HB = 768 * 768;
    const int zz = blockIdx.z;
    const __nv_bfloat16 *Ab, *Bb;
    float* Cp;
    float* Rp = nullptr;
    if (zz < 16) {
        Ab = A1b + (size_t)zz * HB; Bb = A2tb + (size_t)zz * HB;
        Cp = Cr + (size_t)zz * HB;  Rp = Craw + (size_t)zz * HB;
    } else {
        const int z = zz - 16;
        Ab = A2b + (size_t)z * HB; Bb = A1tb + (size_t)z * HB;
        Cp = Cl + (size_t)z * HB;
    }
    const __nv_bfloat16* Ag = Ab + (size_t)blockIdx.y * 128 * 768;
    const __nv_bfloat16* Bg = Bb + (size_t)blockIdx.x * 128 * 768;
    float* Cg = Cp + (size_t)blockIdx.y * 128 * 768 + blockIdx.x * 128;
    float* Rg = Rp ? Rp + (size_t)blockIdx.y * 128 * 768 + blockIdx.x * 128 : nullptr;

    const int rA = (lane & 7) + ((lane >> 3) & 1) * 8;
    const int cA = (lane >> 4) * 8;
    const int rB16 = lane & 15;
    const int cB = (lane >> 4) * 8;

    const int gr0 = tid >> 2, gc0 = (tid & 3) * 8;
    const int gr1 = gr0 + 64;
    const uint32_t dA0 = (uint32_t)(gr0 * SPAD + gc0) * 2;
    const uint32_t dA1 = (uint32_t)(gr1 * SPAD + gc0) * 2;

    float acc[16][4];
#pragma unroll
    for (int i = 0; i < 16; i++)
#pragma unroll
        for (int j = 0; j < 4; j++) acc[i][j] = 0.f;

#pragma unroll
    for (int p = 0; p < 3; p++) {
        const __nv_bfloat16* Ak = Ag + p * 32 + gc0;
        const __nv_bfloat16* Bk = Bg + p * 32 + gc0;
        const uint32_t st = sb + p * STG_B;
        CP16(st + dA0, Ak + (size_t)gr0 * 768);
        CP16(st + dA1, Ak + (size_t)gr1 * 768);
        CP16(st + 10240 + dA0, Bk + (size_t)gr0 * 768);
        CP16(st + 10240 + dA1, Bk + (size_t)gr1 * 768);
        CP_COMMIT();
    }

    for (int kb = 0; kb < 24; kb++) {
        const int cur = kb & 3;
        CP_WAIT2();
        __syncthreads();
        if (kb + 3 < 24) {
            const int nxt = (kb + 3) & 3;
            const __nv_bfloat16* Ak = Ag + (kb + 3) * 32 + gc0;
            const __nv_bfloat16* Bk = Bg + (kb + 3) * 32 + gc0;
            const uint32_t st = sb + nxt * STG_B;
            CP16(st + dA0, Ak + (size_t)gr0 * 768);
            CP16(st + dA1, Ak + (size_t)gr1 * 768);
            CP16(st + 10240 + dA0, Bk + (size_t)gr0 * 768);
            CP16(st + 10240 + dA1, Bk + (size_t)gr1 * 768);
        }
        CP_COMMIT();

        const uint32_t bA = sb + cur * STG_B;
        const uint32_t bB = bA + 10240;
#pragma unroll
        for (int ks = 0; ks < 2; ks++) {
            const int kbase = ks * 16;
            uint32_t af[4][4], bf[4][2];
#pragma unroll
            for (int mi = 0; mi < 4; mi++) {
                uint32_t ad = bA + (uint32_t)((wm + mi * 16 + rA) * SPAD + kbase + cA) * 2;
                LDSM4(af[mi], ad);
            }
#pragma unroll
            for (int p = 0; p < 2; p++) {
                uint32_t r[4];
                uint32_t bd = bB + (uint32_t)((wn + p * 16 + rB16) * SPAD + kbase + cB) * 2;
                LDSM4(r, bd);
                bf[p * 2 + 0][0] = r[0]; bf[p * 2 + 0][1] = r[2];
                bf[p * 2 + 1][0] = r[1]; bf[p * 2 + 1][1] = r[3];
            }
#pragma unroll
            for (int mi = 0; mi < 4; mi++)
#pragma unroll
                for (int ni = 0; ni < 4; ni++)
                    MMA_BF16(acc[mi * 4 + ni], af[mi], bf[ni]);
        }
    }

    const int g = lane >> 2, t2 = (lane & 3) * 2;
#pragma unroll
    for (int mi = 0; mi < 4; mi++) {
#pragma unroll
        for (int ni = 0; ni < 4; ni++) {
            const float* d = acc[mi * 4 + ni];
            const int col = wn + ni * 8 + t2;
            const size_t o0 = (size_t)(wm + mi * 16 + g) * 768 + col;
            const size_t o1 = (size_t)(wm + mi * 16 + g + 8) * 768 + col;
            float2 v0, v1;
            v0.x = __logf(d[0] + EPSF); v0.y = __logf(d[1] + EPSF);
            v1.x = __logf(d[2] + EPSF); v1.y = __logf(d[3] + EPSF);
            *(float2*)(Cg + o0) = v0;
            *(float2*)(Cg + o1) = v1;
            if (Rg) {
                *(float2*)(Rg + o0) = make_float2(d[0], d[1]);
                *(float2*)(Rg + o1) = make_float2(d[2], d[3]);
            }
        }
    }
}

// ---------------------------------------------------------------------------
// Dual-set 128x128x8 register-tiled SGEMM. z < zsplit -> set 1, else set 2
// (set-local z used for the batch/head decomposition). Strides shared.
// ---------------------------------------------------------------------------
__global__ __launch_bounds__(256) void sgemm128(
    const float* __restrict__ A1, const float* __restrict__ B1, float* __restrict__ C1,
    const float* __restrict__ A2, const float* __restrict__ B2, float* __restrict__ C2,
    int lda, size_t sAb, size_t sAh,
    int ldb, size_t sBb, size_t sBh,
    int ldc, size_t sCb, size_t sCh,
    int K, float alpha, int zsplit)
{
    int z = blockIdx.z;
    const float* A; const float* B; float* C;
    if (z < zsplit) { A = A1; B = B1; C = C1; }
    else            { A = A2; B = B2; C = C2; z -= zsplit; }
    const size_t ob = z >> 3, oh = z & 7;
    A += ob * sAb + oh * sAh + (size_t)blockIdx.y * 128 * lda;
    B += ob * sBb + oh * sBh + blockIdx.x * 128;
    C += ob * sCb + oh * sCh + (size_t)blockIdx.y * 128 * ldc + blockIdx.x * 128;

    __shared__ float As[8][128];
    __shared__ float Bs[8][128];

    const int tid  = threadIdx.x;
    const int aRow = tid >> 1, aCol = (tid & 1) * 4;
    const int bRow = tid >> 5, bCol = (tid & 31) * 4;
    const int tx = (tid & 15) * 8, ty = (tid >> 4) * 8;

    float acc[8][8];
#pragma unroll
    for (int i = 0; i < 8; i++)
#pragma unroll
        for (int j = 0; j < 8; j++) acc[i][j] = 0.f;

    for (int k0 = 0; k0 < K; k0 += 8) {
        float4 av = *(const float4*)(A + (size_t)aRow * lda + k0 + aCol);
        As[aCol + 0][aRow] = av.x; As[aCol + 1][aRow] = av.y;
        As[aCol + 2][aRow] = av.z; As[aCol + 3][aRow] = av.w;
        *(float4*)&Bs[bRow][bCol] =
            *(const float4*)(B + (size_t)(k0 + bRow) * ldb + bCol);
        __syncthreads();
#pragma unroll
        for (int k = 0; k < 8; ++k) {
            float4 a0 = *(float4*)&As[k][ty];
            float4 a1 = *(float4*)&As[k][ty + 4];
            float4 b0 = *(float4*)&Bs[k][tx];
            float4 b1 = *(float4*)&Bs[k][tx + 4];
            float ar[8] = {a0.x, a0.y, a0.z, a0.w, a1.x, a1.y, a1.z, a1.w};
            float br[8] = {b0.x, b0.y, b0.z, b0.w, b1.x, b1.y, b1.z, b1.w};
#pragma unroll
            for (int i = 0; i < 8; i++)
#pragma unroll
                for (int j = 0; j < 8; j++)
                    acc[i][j] = fmaf(ar[i], br[j], acc[i][j]);
        }
        __syncthreads();
    }

#pragma unroll
    for (int i = 0; i < 8; i++) {
        *(float4*)&C[(size_t)(ty + i) * ldc + tx] =
            make_float4(alpha * acc[i][0], alpha * acc[i][1],
                        alpha * acc[i][2], alpha * acc[i][3]);
        *(float4*)&C[(size_t)(ty + i) * ldc + tx + 4] =
            make_float4(alpha * acc[i][4], alpha * acc[i][5],
                        alpha * acc[i][6], alpha * acc[i][7]);
    }
}

// ---------------------------------------------------------------------------
// Dual-set 64x64x16 SGEMM (AV products: y_base and y_chain in one launch).
// ---------------------------------------------------------------------------
__global__ __launch_bounds__(256) void sgemm64d(
    const float* __restrict__ A1, const float* __restrict__ B1, float* __restrict__ C1,
    const float* __restrict__ A2, const float* __restrict__ B2, float* __restrict__ C2,
    int lda, size_t sAb, size_t sAh,
    int ldb, size_t sBb, size_t sBh,
    int ldc, size_t sCb, size_t sCh,
    int K, int zsplit)
{
    int z = blockIdx.z;
    const float* A; const float* B; float* C;
    if (z < zsplit) { A = A1; B = B1; C = C1; }
    else            { A = A2; B = B2; C = C2; z -= zsplit; }
    const size_t ob = z >> 3, oh = z & 7;
    A += ob * sAb + oh * sAh + (size_t)blockIdx.y * 64 * lda;
    B += ob * sBb + oh * sBh + blockIdx.x * 64;
    C += ob * sCb + oh * sCh + (size_t)blockIdx.y * 64 * ldc + blockIdx.x * 64;

    __shared__ float As[16][64];
    __shared__ float Bs[16][64];

    const int tid = threadIdx.x;
    const int tx = (tid & 15) * 4, ty = (tid >> 4) * 4;
    const int ar = tid >> 2, ac = (tid & 3) * 4;
    const int br = tid >> 4, bc = (tid & 15) * 4;

    float acc[4][4];
#pragma unroll
    for (int i = 0; i < 4; i++)
#pragma unroll
        for (int j = 0; j < 4; j++) acc[i][j] = 0.f;

    for (int k0 = 0; k0 < K; k0 += 16) {
        float4 av = *(const float4*)(A + (size_t)ar * lda + k0 + ac);
        As[ac + 0][ar] = av.x; As[ac + 1][ar] = av.y;
        As[ac + 2][ar] = av.z; As[ac + 3][ar] = av.w;
        *(float4*)&Bs[br][bc] =
            *(const float4*)(B + (size_t)(k0 + br) * ldb + bc);
        __syncthreads();
#pragma unroll
        for (int k = 0; k < 16; k++) {
            float4 a = *(float4*)&As[k][ty];
            float4 b = *(float4*)&Bs[k][tx];
            float ar4[4] = {a.x, a.y, a.z, a.w};
            float br4[4] = {b.x, b.y, b.z, b.w};
#pragma unroll
            for (int i = 0; i < 4; i++)
#pragma unroll
                for (int j = 0; j < 4; j++)
                    acc[i][j] = fmaf(ar4[i], br4[j], acc[i][j]);
        }
        __syncthreads();
    }

#pragma unroll
    for (int i = 0; i < 4; i++)
        *(float4*)&C[(size_t)(ty + i) * ldc + tx] =
            make_float4(acc[i][0], acc[i][1], acc[i][2], acc[i][3]);
}

// ---------------------------------------------------------------------------
// Output projection with fused combine: out = (Y1 + w*Y2) @ W, w=sigmoid(cl).
// 64x64 tile, K=512. grid (8, 24).
// ---------------------------------------------------------------------------
__global__ __launch_bounds__(256) void proj_kernel(
    const float* __restrict__ Y1, const float* __restrict__ Y2,
    const float* __restrict__ W, float* __restrict__ out,
    const float* __restrict__ chlogit)
{
    const float w = sigmoid_f(chlogit[0]);
    const float* A1 = Y1 + (size_t)blockIdx.y * 64 * 512;
    const float* A2 = Y2 + (size_t)blockIdx.y * 64 * 512;
    const float* B  = W + blockIdx.x * 64;
    float* C = out + (size_t)blockIdx.y * 64 * 512 + blockIdx.x * 64;

    __shared__ float As[16][64];
    __shared__ float Bs[16][64];

    const int tid = threadIdx.x;
    const int tx = (tid & 15) * 4, ty = (tid >> 4) * 4;
    const int ar = tid >> 2, ac = (tid & 3) * 4;
    const int br = tid >> 4, bc = (tid & 15) * 4;

    float acc[4][4];
#pragma unroll
    for (int i = 0; i < 4; i++)
#pragma unroll
        for (int j = 0; j < 4; j++) acc[i][j] = 0.f;

    for (int k0 = 0; k0 < 512; k0 += 16) {
        float4 a1 = *(const float4*)(A1 + (size_t)ar * 512 + k0 + ac);
        float4 a2 = *(const float4*)(A2 + (size_t)ar * 512 + k0 + ac);
        As[ac + 0][ar] = fmaf(w, a2.x, a1.x);
        As[ac + 1][ar] = fmaf(w, a2.y, a1.y);
        As[ac + 2][ar] = fmaf(w, a2.z, a1.z);
        As[ac + 3][ar] = fmaf(w, a2.w, a1.w);
        *(float4*)&Bs[br][bc] =
            *(const float4*)(B + (size_t)(k0 + br) * 512 + bc);
        __syncthreads();
#pragma unroll
        for (int k = 0; k < 16; k++) {
            float4 a = *(float4*)&As[k][ty];
            float4 b = *(float4*)&Bs[k][tx];
            float ar4[4] = {a.x, a.y, a.z, a.w};
            float br4[4] = {b.x, b.y, b.z, b.w};
#pragma unroll
            for (int i = 0; i < 4; i++)
#pragma unroll
                for (int j = 0; j < 4; j++)
                    acc[i][j] = fmaf(ar4[i], br4[j], acc[i][j]);
        }
        __syncthreads();
    }

#pragma unroll
    for (int i = 0; i < 4; i++)
        *(float4*)&C[(size_t)(ty + i) * 512 + tx] =
            make_float4(acc[i][0], acc[i][1], acc[i][2], acc[i][3]);
}

// ---------------------------------------------------------------------------
// Merged transpose of the K slice for both raw buffers. z<16 -> set 1.
// ---------------------------------------------------------------------------
__global__ void transposeK(const float* __restrict__ raw1, float* __restrict__ kT1,
                           const float* __restrict__ raw2, float* __restrict__ kT2)
{
    __shared__ float tile[32][33];
    const int zz = blockIdx.z;
    const float* raw = (zz < 16) ? raw1 : raw2;
    float* kT = (zz < 16) ? kT1 : kT2;
    const int bh = zz & 15, b = bh >> 3, h = bh & 7;
    const int n0 = blockIdx.x * 32, d0 = blockIdx.y * 32;
    const float* src = raw + (size_t)b * 768 * 1536 + 512 + h * 64;
#pragma unroll
    for (int i = 0; i < 4; i++) {
        int n = n0 + threadIdx.y + i * 8;
        tile[threadIdx.y + i * 8][threadIdx.x] =
            src[(size_t)n * 1536 + d0 + threadIdx.x];
    }
    __syncthreads();
    float* dst = kT + (size_t)bh * 64 * 768;
#pragma unroll
    for (int i = 0; i < 4; i++) {
        int d = d0 + threadIdx.y + i * 8;
        dst[(size_t)d * 768 + n0 + threadIdx.x] = tile[threadIdx.x][threadIdx.y + i * 8];
    }
}

// ---------------------------------------------------------------------------
// Transpose + bf16-convert; merged pair.
// ---------------------------------------------------------------------------
__global__ void transpose_cvt(const float* __restrict__ in1,
                              __nv_bfloat16* __restrict__ out1,
                              const float* __restrict__ in2,
                              __nv_bfloat16* __restrict__ out2)
{
    __shared__ float t[32][33];
    const int zz = blockIdx.z;
    const float* in = (zz < 16) ? in1 : in2;
    __nv_bfloat16* out = (zz < 16) ? out1 : out2;
    const size_t base = (size_t)(zz & 15) * 768 * 768;
    const int x0 = blockIdx.x * 32, y0 = blockIdx.y * 32;
#pragma unroll
    for (int i = 0; i < 4; i++)
        t[threadIdx.y + i * 8][threadIdx.x] =
            in[base + (size_t)(y0 + threadIdx.y + i * 8) * 768 + x0 + threadIdx.x];
    __syncthreads();
#pragma unroll
    for (int i = 0; i < 4; i++)
        out[base + (size_t)(x0 + threadIdx.y + i * 8) * 768 + y0 + threadIdx.x] =
            __float2bfloat16_rn(t[threadIdx.x][threadIdx.y + i * 8]);
}

// ---------------------------------------------------------------------------
// Row softmax, 768 cols; merged pair (second pair optional).
// ---------------------------------------------------------------------------
__global__ __launch_bounds__(256) void softmax768(
    const float* __restrict__ in1, float* __restrict__ out1,
    __nv_bfloat16* __restrict__ outb1,
    const float* __restrict__ in2, float* __restrict__ out2,
    __nv_bfloat16* __restrict__ outb2)
{
    size_t row = blockIdx.x;
    const float* in = in1; float* out = out1; __nv_bfloat16* outb = outb1;
    if (row >= 12288) { row -= 12288; in = in2; out = out2; outb = outb2; }
    const float* p = in + row * 768;
    const int t = threadIdx.x;
    float v0 = p[t], v1 = p[t + 256], v2 = p[t + 512];

    __shared__ float red[256];
    red[t] = fmaxf(fmaxf(v0, v1), v2);
    __syncthreads();
#pragma unroll
    for (int s = 128; s > 0; s >>= 1) {
        if (t < s) red[t] = fmaxf(red[t], red[t + s]);
        __syncthreads();
    }
    const float m = red[0];
    __syncthreads();

    float e0 = __expf(v0 - m), e1 = __expf(v1 - m), e2 = __expf(v2 - m);
    red[t] = e0 + e1 + e2;
    __syncthreads();
#pragma unroll
    for (int s = 128; s > 0; s >>= 1) {
        if (t < s) red[t] += red[t + s];
        __syncthreads();
    }
    const float inv = 1.0f / red[0];
    e0 *= inv; e1 *= inv; e2 *= inv;
    float* q = out + row * 768;
    q[t] = e0; q[t + 256] = e1; q[t + 512] = e2;
    if (outb) {
        __nv_bfloat16* qb = outb + row * 768;
        qb[t] = __float2bfloat16_rn(e0);
        qb[t + 256] = __float2bfloat16_rn(e1);
        qb[t + 512] = __float2bfloat16_rn(e2);
    }
}

// ---------------------------------------------------------------------------
// Fused gate conv + Smix (fast-math MUFU version).
// ---------------------------------------------------------------------------
__global__ __launch_bounds__(256) void mix_kernel(
    const float* __restrict__ S1, const float* __restrict__ S2,
    const float* __restrict__ Cr, const float* __restrict__ Cl,
    float* __restrict__ Smix,
    const float* __restrict__ w1, const float* __restrict__ b1,
    const float* __restrict__ w2, const float* __restrict__ b2)
{
    __shared__ float T1[64][65];
    __shared__ float T2[64][65];
    __shared__ float sw1[96], sb1[16], sw2[64], sb2[4];

    const int tid = threadIdx.x;
    if (tid < 96) sw1[tid] = w1[tid];
    if (tid < 16) sb1[tid] = b1[tid];
    if (tid < 64) sw2[tid] = w2[tid];
    if (tid < 4)  sb2[tid] = b2[tid];

    const size_t base = (size_t)blockIdx.z * 768 * 768;
    const int nt = blockIdx.y * 64, mt = blockIdx.x * 64;

#pragma unroll
    for (int u = 0; u < 4; u++) {
        int f = tid + u * 256;
        int r = f >> 4, c4 = (f & 15) * 4;
        size_t off = base + (size_t)(mt + r) * 768 + nt + c4;
        float4 a = *(const float4*)(S1 + off);
        T1[c4 + 0][r] = a.x; T1[c4 + 1][r] = a.y; T1[c4 + 2][r] = a.z; T1[c4 + 3][r] = a.w;
        float4 c = *(const float4*)(S2 + off);
        T2[c4 + 0][r] = c.x; T2[c4 + 1][r] = c.y; T2[c4 + 2][r] = c.z; T2[c4 + 3][r] = c.w;
    }
    __syncthreads();

#pragma unroll 1
    for (int u = 0; u < 16; u++) {
        int e = tid + u * 256;
        int i = e >> 6, j = e & 63;
        size_t idx = base + (size_t)(nt + i) * 768 + mt + j;
        float s1 = S1[idx], s2 = S2[idx];
        float s1t = T1[i][j], s2t = T2[i][j];
        float cr = Cr[idx], cl = Cl[idx];
        float feat[6] = {s1, s2, s1t, s2t, cr, cl};

        float g[4] = {sb2[0], sb2[1], sb2[2], sb2[3]};
#pragma unroll
        for (int o = 0; o < 16; o++) {
            float hv = sb1[o];
#pragma unroll
            for (int c = 0; c < 6; c++) hv = fmaf(feat[c], sw1[o * 6 + c], hv);
            float th = tanh_apx(0.7978845608028654f * (hv + 0.044715f * hv * hv * hv));
            float hid = 0.5f * hv * (1.0f + th);
#pragma unroll
            for (int q = 0; q < 4; q++) g[q] = fmaf(hid, sw2[q * 16 + o], g[q]);
        }
        float gA = sigmoid_f(g[0]);
        float gO = sigmoid_f(g[1]);
        float gN = sigmoid_f(g[2]);
        float gC = sigmoid_f(g[3]);
        float mx = fmaxf(s1, s2), mn = fminf(s1, s2);
        float lae = mx + __logf(1.0f + __expf(mn - mx));
        Smix[idx] = s1 + gA * s2 + gO * (lae - s1) - gN * (0.5f * s2) + gC * cr;
    }
}

// ---------------------------------------------------------------------------
extern "C" void kernel_launch(void* const* d_in, const int* in_sizes, int n_in,
                              void* d_out, int out_size)
{
    const float* x        = (const float*)d_in[0];
    const float* qkv1_w   = (const float*)d_in[1];
    const float* qkv2_w   = (const float*)d_in[2];
    const float* proj_w   = (const float*)d_in[3];
    const float* conv1_w  = (const float*)d_in[4];
    const float* conv1_b  = (const float*)d_in[5];
    const float* conv2_w  = (const float*)d_in[6];
    const float* conv2_b  = (const float*)d_in[7];
    const float* chlogit  = (const float*)d_in[8];
    float* out = (float*)d_out;

    float *p_raw1, *p_raw2, *p_kT1, *p_kT2, *p_S1, *p_S2, *p_A1, *p_A2;
    float *p_Cr, *p_Cl, *p_Smix, *p_y2, *p_y;
    __nv_bfloat16 *p_A1b, *p_A2b, *p_A1tb, *p_A2tb;
    cudaGetSymbolAddress((void**)&p_raw1, g_raw1);
    cudaGetSymbolAddress((void**)&p_raw2, g_raw2);
    cudaGetSymbolAddress((void**)&p_kT1, g_kT1);
    cudaGetSymbolAddress((void**)&p_kT2, g_kT2);
    cudaGetSymbolAddress((void**)&p_S1, g_S1);
    cudaGetSymbolAddress((void**)&p_S2, g_S2);
    cudaGetSymbolAddress((void**)&p_A1, g_A1);
    cudaGetSymbolAddress((void**)&p_A2, g_A2);
    cudaGetSymbolAddress((void**)&p_Cr, g_Cr);
    cudaGetSymbolAddress((void**)&p_Cl, g_Cl);
    cudaGetSymbolAddress((void**)&p_Smix, g_Smix);
    cudaGetSymbolAddress((void**)&p_y2, g_y2);
    cudaGetSymbolAddress((void**)&p_y, g_y);
    cudaGetSymbolAddress((void**)&p_A1b, g_A1b);
    cudaGetSymbolAddress((void**)&p_A2b, g_A2b);
    cudaGetSymbolAddress((void**)&p_A1tb, g_A1tb);
    cudaGetSymbolAddress((void**)&p_A2tb, g_A2tb);

    cudaFuncSetAttribute(hmma_logC,
                         cudaFuncAttributeMaxDynamicSharedMemorySize, HSM_TOTAL);

    const size_t SB = 768 * 768;
    const size_t RB = 768 * 1536;
    const size_t VB = 768 * 64;
    const size_t YB = 768 * 512;

    // 1) both QKV projections in one launch (z=2, 288 CTAs)
    sgemm128<<<dim3(12, 12, 2), 256>>>(x, qkv1_w, p_raw1,
                                       x, qkv2_w, p_raw2,
                                       512, 0, 0, 1536, 0, 0, 1536, 0, 0,
                                       512, 1.0f, 1);

    // 2) both K transposes in one launch
    transposeK<<<dim3(24, 2, 32), dim3(32, 8)>>>(p_raw1, p_kT1, p_raw2, p_kT2);

    // 3) S1 & S2 in one launch (z=32, 1152 CTAs)
    sgemm128<<<dim3(6, 6, 32), 256>>>(p_raw1, p_kT1, p_S1,
                                      p_raw2, p_kT2, p_S2,
                                      1536, RB, 64, 768, 8 * VB, VB,
                                      768, 8 * SB, SB,
                                      64, 0.125f, 16);

    // 4) A1/A2 softmax (+ bf16 copies) — merged
    softmax768<<<24576, 256>>>(p_S1, p_A1, p_A1b, p_S2, p_A2, p_A2b);

    // 4b) transposed bf16 copies — merged
    transpose_cvt<<<dim3(24, 24, 32), dim3(32, 8)>>>(p_A1, p_A1tb, p_A2, p_A2tb);

    // 5) Cr & Cl (+ raw C_right into g_A1, A1 fp32 is dead from here)
    hmma_logC<<<dim3(6, 6, 32), 256, HSM_TOTAL>>>(p_A1b, p_A2tb, p_A2b, p_A1tb,
                                                  p_Cr, p_Cl, p_A1);

    // 6) fused gate conv + Smix
    mix_kernel<<<dim3(12, 12, 16), 256>>>(p_S1, p_S2, p_Cr, p_Cl, p_Smix,
                                          conv1_w, conv1_b, conv2_w, conv2_b);

    // 7) A = softmax(Smix) in place
    softmax768<<<12288, 256>>>(p_Smix, p_Smix, nullptr,
                               p_Smix, p_Smix, nullptr);

    // 8) y_base = A @ v1  ∥  y_chain = Craw @ v2  (one launch, 384 CTAs)
    sgemm64d<<<dim3(1, 12, 32), 256>>>(p_Smix, p_raw1 + 1024, p_y,
                                       p_A1,   p_raw2 + 1024, p_y2,
                                       768, 8 * SB, SB,
                                       1536, RB, 64,
                                       512, YB, 64,
                                       768, 16);

    // 9) out = (y_base + sigmoid(chain_logit) * y_chain) @ proj_w
    proj_kernel<<<dim3(8, 24), 256>>>(p_y, p_y2, proj_w, out, chlogit);
}

// round 17
// speedup vs baseline: 1.2375x; 1.0003x over previous
#include <cuda_runtime.h>
#include <cuda_bf16.h>
#include <cstdint>
#include <stdint.h>
#include <math.h>

#define EPSF 1e-6f

// ---------------- scratch (device globals; no allocation allowed) ----------
__device__ float g_raw1[1536 * 1536];      // x @ qkv1_w   [B*N, 3*D]
__device__ float g_raw2[1536 * 1536];      // x @ qkv2_w
__device__ float g_kT1[16 * 64 * 768];     // k1 transposed per head
__device__ float g_kT2[16 * 64 * 768];
__device__ float g_S1[16 * 768 * 768];
__device__ float g_S2[16 * 768 * 768];
__device__ float g_A1[16 * 768 * 768];     // A1 fp32; later reused as Craw
__device__ float g_A2[16 * 768 * 768];
__device__ float g_Cr[16 * 768 * 768];     // log(A1@A2 + eps)
__device__ float g_Cl[16 * 768 * 768];     // log(A2@A1 + eps)
__device__ float g_Smix[16 * 768 * 768];   // Smix -> softmax in place
__device__ float g_y2[1536 * 512];         // y_chain = Craw @ v2
__device__ float g_y[1536 * 512];          // y_base
// bf16 copies for the HMMA path
__device__ __nv_bfloat16 g_A1b[16 * 768 * 768];
__device__ __nv_bfloat16 g_A2b[16 * 768 * 768];
__device__ __nv_bfloat16 g_A1tb[16 * 768 * 768];
__device__ __nv_bfloat16 g_A2tb[16 * 768 * 768];

// ============================ helpers =======================================
__device__ __forceinline__ uint32_t smem_u32(const void* p) {
    uint32_t a;
    asm("{ .reg .u64 t; cvta.to.shared.u64 t, %1; cvt.u32.u64 %0, t; }"
        : "=r"(a) : "l"(p));
    return a;
}
__device__ __forceinline__ float tanh_apx(float x) {
    float y;
    asm("tanh.approx.f32 %0, %1;" : "=f"(y) : "f"(x));
    return y;
}
__device__ __forceinline__ float sigmoid_f(float x) {
    return 0.5f * tanh_apx(0.5f * x) + 0.5f;
}

#define LDSM4(r, addr) \
    asm volatile("ldmatrix.sync.aligned.m8n8.x4.shared.b16 {%0,%1,%2,%3}, [%4];" \
        : "=r"((r)[0]), "=r"((r)[1]), "=r"((r)[2]), "=r"((r)[3]) : "r"(addr))
#define MMA_BF16(d, a, b) \
    asm volatile("mma.sync.aligned.m16n8k16.row.col.f32.bf16.bf16.f32 " \
        "{%0,%1,%2,%3}, {%4,%5,%6,%7}, {%8,%9}, {%0,%1,%2,%3};" \
        : "+f"((d)[0]), "+f"((d)[1]), "+f"((d)[2]), "+f"((d)[3]) \
        : "r"((a)[0]), "r"((a)[1]), "r"((a)[2]), "r"((a)[3]), \
          "r"((b)[0]), "r"((b)[1]))
#define CP16(dst, src) \
    asm volatile("cp.async.cg.shared.global [%0], [%1], 16;" \
        :: "r"(dst), "l"(src))
#define CP_COMMIT() asm volatile("cp.async.commit_group;" ::: "memory")
#define CP_WAIT2()  asm volatile("cp.async.wait_group 2;" ::: "memory")

// ---------------------------------------------------------------------------
// HMMA bf16 GEMM, merged Cr/Cl, fused log epilogue. For z<16 also stores the
// RAW product (fp32) into Craw — reused later as y_chain = Craw @ v2.
// CTA 128x128, 8 warps, warp tile 64x32, 4-stage cp.async pipeline.
// ---------------------------------------------------------------------------
#define SPAD 40
#define STG_B 20480
#define HSM_TOTAL (4 * STG_B)

__global__ __launch_bounds__(256) void hmma_logC(
    const __nv_bfloat16* __restrict__ A1b, const __nv_bfloat16* __restrict__ A2tb,
    const __nv_bfloat16* __restrict__ A2b, const __nv_bfloat16* __restrict__ A1tb,
    float* __restrict__ Cr, float* __restrict__ Cl, float* __restrict__ Craw)
{
    extern __shared__ __align__(16) char dsm[];
    const uint32_t sb = smem_u32(dsm);

    const int tid = threadIdx.x;
    const int wid = tid >> 5, lane = tid & 31;
    const int wm = (wid & 1) * 64;
    const int wn = (wid >> 1) * 32;

    const size_t HB = 768 * 768;
    const int zz = blockIdx.z;
    const __nv_bfloat16 *Ab, *Bb;
    float* Cp;
    float* Rp = nullptr;
    if (zz < 16) {
        Ab = A1b + (size_t)zz * HB; Bb = A2tb + (size_t)zz * HB;
        Cp = Cr + (size_t)zz * HB;  Rp = Craw + (size_t)zz * HB;
    } else {
        const int z = zz - 16;
        Ab = A2b + (size_t)z * HB; Bb = A1tb + (size_t)z * HB;
        Cp = Cl + (size_t)z * HB;
    }
    const __nv_bfloat16* Ag = Ab + (size_t)blockIdx.y * 128 * 768;
    const __nv_bfloat16* Bg = Bb + (size_t)blockIdx.x * 128 * 768;
    float* Cg = Cp + (size_t)blockIdx.y * 128 * 768 + blockIdx.x * 128;
    float* Rg = Rp ? Rp + (size_t)blockIdx.y * 128 * 768 + blockIdx.x * 128 : nullptr;

    const int rA = (lane & 7) + ((lane >> 3) & 1) * 8;
    const int cA = (lane >> 4) * 8;
    const int rB16 = lane & 15;
    const int cB = (lane >> 4) * 8;

    const int gr0 = tid >> 2, gc0 = (tid & 3) * 8;
    const int gr1 = gr0 + 64;
    const uint32_t dA0 = (uint32_t)(gr0 * SPAD + gc0) * 2;
    const uint32_t dA1 = (uint32_t)(gr1 * SPAD + gc0) * 2;

    float acc[16][4];
#pragma unroll
    for (int i = 0; i < 16; i++)
#pragma unroll
        for (int j = 0; j < 4; j++) acc[i][j] = 0.f;

#pragma unroll
    for (int p = 0; p < 3; p++) {
        const __nv_bfloat16* Ak = Ag + p * 32 + gc0;
        const __nv_bfloat16* Bk = Bg + p * 32 + gc0;
        const uint32_t st = sb + p * STG_B;
        CP16(st + dA0, Ak + (size_t)gr0 * 768);
        CP16(st + dA1, Ak + (size_t)gr1 * 768);
        CP16(st + 10240 + dA0, Bk + (size_t)gr0 * 768);
        CP16(st + 10240 + dA1, Bk + (size_t)gr1 * 768);
        CP_COMMIT();
    }

    for (int kb = 0; kb < 24; kb++) {
        const int cur = kb & 3;
        CP_WAIT2();
        __syncthreads();
        if (kb + 3 < 24) {
            const int nxt = (kb + 3) & 3;
            const __nv_bfloat16* Ak = Ag + (kb + 3) * 32 + gc0;
            const __nv_bfloat16* Bk = Bg + (kb + 3) * 32 + gc0;
            const uint32_t st = sb + nxt * STG_B;
            CP16(st + dA0, Ak + (size_t)gr0 * 768);
            CP16(st + dA1, Ak + (size_t)gr1 * 768);
            CP16(st + 10240 + dA0, Bk + (size_t)gr0 * 768);
            CP16(st + 10240 + dA1, Bk + (size_t)gr1 * 768);
        }
        CP_COMMIT();

        const uint32_t bA = sb + cur * STG_B;
        const uint32_t bB = bA + 10240;
#pragma unroll
        for (int ks = 0; ks < 2; ks++) {
            const int kbase = ks * 16;
            uint32_t af[4][4], bf[4][2];
#pragma unroll
            for (int mi = 0; mi < 4; mi++) {
                uint32_t ad = bA + (uint32_t)((wm + mi * 16 + rA) * SPAD + kbase + cA) * 2;
                LDSM4(af[mi], ad);
            }
#pragma unroll
            for (int p = 0; p < 2; p++) {
                uint32_t r[4];
                uint32_t bd = bB + (uint32_t)((wn + p * 16 + rB16) * SPAD + kbase + cB) * 2;
                LDSM4(r, bd);
                bf[p * 2 + 0][0] = r[0]; bf[p * 2 + 0][1] = r[2];
                bf[p * 2 + 1][0] = r[1]; bf[p * 2 + 1][1] = r[3];
            }
#pragma unroll
            for (int mi = 0; mi < 4; mi++)
#pragma unroll
                for (int ni = 0; ni < 4; ni++)
                    MMA_BF16(acc[mi * 4 + ni], af[mi], bf[ni]);
        }
    }

    const int g = lane >> 2, t2 = (lane & 3) * 2;
#pragma unroll
    for (int mi = 0; mi < 4; mi++) {
#pragma unroll
        for (int ni = 0; ni < 4; ni++) {
            const float* d = acc[mi * 4 + ni];
            const int col = wn + ni * 8 + t2;
            const size_t o0 = (size_t)(wm + mi * 16 + g) * 768 + col;
            const size_t o1 = (size_t)(wm + mi * 16 + g + 8) * 768 + col;
            float2 v0, v1;
            v0.x = __logf(d[0] + EPSF); v0.y = __logf(d[1] + EPSF);
            v1.x = __logf(d[2] + EPSF); v1.y = __logf(d[3] + EPSF);
            *(float2*)(Cg + o0) = v0;
            *(float2*)(Cg + o1) = v1;
            if (Rg) {
                *(float2*)(Rg + o0) = make_float2(d[0], d[1]);
                *(float2*)(Rg + o1) = make_float2(d[2], d[3]);
            }
        }
    }
}

// ---------------------------------------------------------------------------
// Dual-set 128x128x8 register-tiled SGEMM. z < zsplit -> set 1, else set 2
// (set-local z used for the batch/head decomposition). Strides shared.
// ---------------------------------------------------------------------------
__global__ __launch_bounds__(256) void sgemm128(
    const float* __restrict__ A1, const float* __restrict__ B1, float* __restrict__ C1,
    const float* __restrict__ A2, const float* __restrict__ B2, float* __restrict__ C2,
    int lda, size_t sAb, size_t sAh,
    int ldb, size_t sBb, size_t sBh,
    int ldc, size_t sCb, size_t sCh,
    int K, float alpha, int zsplit)
{
    int z = blockIdx.z;
    const float* A; const float* B; float* C;
    if (z < zsplit) { A = A1; B = B1; C = C1; }
    else            { A = A2; B = B2; C = C2; z -= zsplit; }
    const size_t ob = z >> 3, oh = z & 7;
    A += ob * sAb + oh * sAh + (size_t)blockIdx.y * 128 * lda;
    B += ob * sBb + oh * sBh + blockIdx.x * 128;
    C += ob * sCb + oh * sCh + (size_t)blockIdx.y * 128 * ldc + blockIdx.x * 128;

    __shared__ float As[8][128];
    __shared__ float Bs[8][128];

    const int tid  = threadIdx.x;
    const int aRow = tid >> 1, aCol = (tid & 1) * 4;
    const int bRow = tid >> 5, bCol = (tid & 31) * 4;
    const int tx = (tid & 15) * 8, ty = (tid >> 4) * 8;

    float acc[8][8];
#pragma unroll
    for (int i = 0; i < 8; i++)
#pragma unroll
        for (int j = 0; j < 8; j++) acc[i][j] = 0.f;

    for (int k0 = 0; k0 < K; k0 += 8) {
        float4 av = *(const float4*)(A + (size_t)aRow * lda + k0 + aCol);
        As[aCol + 0][aRow] = av.x; As[aCol + 1][aRow] = av.y;
        As[aCol + 2][aRow] = av.z; As[aCol + 3][aRow] = av.w;
        *(float4*)&Bs[bRow][bCol] =
            *(const float4*)(B + (size_t)(k0 + bRow) * ldb + bCol);
        __syncthreads();
#pragma unroll
        for (int k = 0; k < 8; ++k) {
            float4 a0 = *(float4*)&As[k][ty];
            float4 a1 = *(float4*)&As[k][ty + 4];
            float4 b0 = *(float4*)&Bs[k][tx];
            float4 b1 = *(float4*)&Bs[k][tx + 4];
            float ar[8] = {a0.x, a0.y, a0.z, a0.w, a1.x, a1.y, a1.z, a1.w};
            float br[8] = {b0.x, b0.y, b0.z, b0.w, b1.x, b1.y, b1.z, b1.w};
#pragma unroll
            for (int i = 0; i < 8; i++)
#pragma unroll
                for (int j = 0; j < 8; j++)
                    acc[i][j] = fmaf(ar[i], br[j], acc[i][j]);
        }
        __syncthreads();
    }

#pragma unroll
    for (int i = 0; i < 8; i++) {
        *(float4*)&C[(size_t)(ty + i) * ldc + tx] =
            make_float4(alpha * acc[i][0], alpha * acc[i][1],
                        alpha * acc[i][2], alpha * acc[i][3]);
        *(float4*)&C[(size_t)(ty + i) * ldc + tx + 4] =
            make_float4(alpha * acc[i][4], alpha * acc[i][5],
                        alpha * acc[i][6], alpha * acc[i][7]);
    }
}

// ---------------------------------------------------------------------------
// Dual-set 64x64x16 SGEMM (AV products: y_base and y_chain in one launch).
// ---------------------------------------------------------------------------
__global__ __launch_bounds__(256) void sgemm64d(
    const float* __restrict__ A1, const float* __restrict__ B1, float* __restrict__ C1,
    const float* __restrict__ A2, const float* __restrict__ B2, float* __restrict__ C2,
    int lda, size_t sAb, size_t sAh,
    int ldb, size_t sBb, size_t sBh,
    int ldc, size_t sCb, size_t sCh,
    int K, int zsplit)
{
    int z = blockIdx.z;
    const float* A; const float* B; float* C;
    if (z < zsplit) { A = A1; B = B1; C = C1; }
    else            { A = A2; B = B2; C = C2; z -= zsplit; }
    const size_t ob = z >> 3, oh = z & 7;
    A += ob * sAb + oh * sAh + (size_t)blockIdx.y * 64 * lda;
    B += ob * sBb + oh * sBh + blockIdx.x * 64;
    C += ob * sCb + oh * sCh + (size_t)blockIdx.y * 64 * ldc + blockIdx.x * 64;

    __shared__ float As[16][64];
    __shared__ float Bs[16][64];

    const int tid = threadIdx.x;
    const int tx = (tid & 15) * 4, ty = (tid >> 4) * 4;
    const int ar = tid >> 2, ac = (tid & 3) * 4;
    const int br = tid >> 4, bc = (tid & 15) * 4;

    float acc[4][4];
#pragma unroll
    for (int i = 0; i < 4; i++)
#pragma unroll
        for (int j = 0; j < 4; j++) acc[i][j] = 0.f;

    for (int k0 = 0; k0 < K; k0 += 16) {
        float4 av = *(const float4*)(A + (size_t)ar * lda + k0 + ac);
        As[ac + 0][ar] = av.x; As[ac + 1][ar] = av.y;
        As[ac + 2][ar] = av.z; As[ac + 3][ar] = av.w;
        *(float4*)&Bs[br][bc] =
            *(const float4*)(B + (size_t)(k0 + br) * ldb + bc);
        __syncthreads();
#pragma unroll
        for (int k = 0; k < 16; k++) {
            float4 a = *(float4*)&As[k][ty];
            float4 b = *(float4*)&Bs[k][tx];
            float ar4[4] = {a.x, a.y, a.z, a.w};
            float br4[4] = {b.x, b.y, b.z, b.w};
#pragma unroll
            for (int i = 0; i < 4; i++)
#pragma unroll
                for (int j = 0; j < 4; j++)
                    acc[i][j] = fmaf(ar4[i], br4[j], acc[i][j]);
        }
        __syncthreads();
    }

#pragma unroll
    for (int i = 0; i < 4; i++)
        *(float4*)&C[(size_t)(ty + i) * ldc + tx] =
            make_float4(acc[i][0], acc[i][1], acc[i][2], acc[i][3]);
}

// ---------------------------------------------------------------------------
// Output projection with fused combine: out = (Y1 + w*Y2) @ W, w=sigmoid(cl).
// 64x64 tile, K=512. grid (8, 24).
// ---------------------------------------------------------------------------
__global__ __launch_bounds__(256) void proj_kernel(
    const float* __restrict__ Y1, const float* __restrict__ Y2,
    const float* __restrict__ W, float* __restrict__ out,
    const float* __restrict__ chlogit)
{
    const float w = sigmoid_f(chlogit[0]);
    const float* A1 = Y1 + (size_t)blockIdx.y * 64 * 512;
    const float* A2 = Y2 + (size_t)blockIdx.y * 64 * 512;
    const float* B  = W + blockIdx.x * 64;
    float* C = out + (size_t)blockIdx.y * 64 * 512 + blockIdx.x * 64;

    __shared__ float As[16][64];
    __shared__ float Bs[16][64];

    const int tid = threadIdx.x;
    const int tx = (tid & 15) * 4, ty = (tid >> 4) * 4;
    const int ar = tid >> 2, ac = (tid & 3) * 4;
    const int br = tid >> 4, bc = (tid & 15) * 4;

    float acc[4][4];
#pragma unroll
    for (int i = 0; i < 4; i++)
#pragma unroll
        for (int j = 0; j < 4; j++) acc[i][j] = 0.f;

    for (int k0 = 0; k0 < 512; k0 += 16) {
        float4 a1 = *(const float4*)(A1 + (size_t)ar * 512 + k0 + ac);
        float4 a2 = *(const float4*)(A2 + (size_t)ar * 512 + k0 + ac);
        As[ac + 0][ar] = fmaf(w, a2.x, a1.x);
        As[ac + 1][ar] = fmaf(w, a2.y, a1.y);
        As[ac + 2][ar] = fmaf(w, a2.z, a1.z);
        As[ac + 3][ar] = fmaf(w, a2.w, a1.w);
        *(float4*)&Bs[br][bc] =
            *(const float4*)(B + (size_t)(k0 + br) * 512 + bc);
        __syncthreads();
#pragma unroll
        for (int k = 0; k < 16; k++) {
            float4 a = *(float4*)&As[k][ty];
            float4 b = *(float4*)&Bs[k][tx];
            float ar4[4] = {a.x, a.y, a.z, a.w};
            float br4[4] = {b.x, b.y, b.z, b.w};
#pragma unroll
            for (int i = 0; i < 4; i++)
#pragma unroll
                for (int j = 0; j < 4; j++)
                    acc[i][j] = fmaf(ar4[i], br4[j], acc[i][j]);
        }
        __syncthreads();
    }

#pragma unroll
    for (int i = 0; i < 4; i++)
        *(float4*)&C[(size_t)(ty + i) * 512 + tx] =
            make_float4(acc[i][0], acc[i][1], acc[i][2], acc[i][3]);
}

// ---------------------------------------------------------------------------
// Merged transpose of the K slice for both raw buffers. z<16 -> set 1.
// ---------------------------------------------------------------------------
__global__ void transposeK(const float* __restrict__ raw1, float* __restrict__ kT1,
                           const float* __restrict__ raw2, float* __restrict__ kT2)
{
    __shared__ float tile[32][33];
    const int zz = blockIdx.z;
    const float* raw = (zz < 16) ? raw1 : raw2;
    float* kT = (zz < 16) ? kT1 : kT2;
    const int bh = zz & 15, b = bh >> 3, h = bh & 7;
    const int n0 = blockIdx.x * 32, d0 = blockIdx.y * 32;
    const float* src = raw + (size_t)b * 768 * 1536 + 512 + h * 64;
#pragma unroll
    for (int i = 0; i < 4; i++) {
        int n = n0 + threadIdx.y + i * 8;
        tile[threadIdx.y + i * 8][threadIdx.x] =
            src[(size_t)n * 1536 + d0 + threadIdx.x];
    }
    __syncthreads();
    float* dst = kT + (size_t)bh * 64 * 768;
#pragma unroll
    for (int i = 0; i < 4; i++) {
        int d = d0 + threadIdx.y + i * 8;
        dst[(size_t)d * 768 + n0 + threadIdx.x] = tile[threadIdx.x][threadIdx.y + i * 8];
    }
}

// ---------------------------------------------------------------------------
// Transpose + bf16-convert; merged pair.
// ---------------------------------------------------------------------------
__global__ void transpose_cvt(const float* __restrict__ in1,
                              __nv_bfloat16* __restrict__ out1,
                              const float* __restrict__ in2,
                              __nv_bfloat16* __restrict__ out2)
{
    __shared__ float t[32][33];
    const int zz = blockIdx.z;
    const float* in = (zz < 16) ? in1 : in2;
    __nv_bfloat16* out = (zz < 16) ? out1 : out2;
    const size_t base = (size_t)(zz & 15) * 768 * 768;
    const int x0 = blockIdx.x * 32, y0 = blockIdx.y * 32;
#pragma unroll
    for (int i = 0; i < 4; i++)
        t[threadIdx.y + i * 8][threadIdx.x] =
            in[base + (size_t)(y0 + threadIdx.y + i * 8) * 768 + x0 + threadIdx.x];
    __syncthreads();
#pragma unroll
    for (int i = 0; i < 4; i++)
        out[base + (size_t)(x0 + threadIdx.y + i * 8) * 768 + y0 + threadIdx.x] =
            __float2bfloat16_rn(t[threadIdx.x][threadIdx.y + i * 8]);
}

// ---------------------------------------------------------------------------
// Row softmax, 768 cols; merged pair (second pair optional).
// ---------------------------------------------------------------------------
__global__ __launch_bounds__(256) void softmax768(
    const float* __restrict__ in1, float* __restrict__ out1,
    __nv_bfloat16* __restrict__ outb1,
    const float* __restrict__ in2, float* __restrict__ out2,
    __nv_bfloat16* __restrict__ outb2)
{
    size_t row = blockIdx.x;
    const float* in = in1; float* out = out1; __nv_bfloat16* outb = outb1;
    if (row >= 12288) { row -= 12288; in = in2; out = out2; outb = outb2; }
    const float* p = in + row * 768;
    const int t = threadIdx.x;
    float v0 = p[t], v1 = p[t + 256], v2 = p[t + 512];

    __shared__ float red[256];
    red[t] = fmaxf(fmaxf(v0, v1), v2);
    __syncthreads();
#pragma unroll
    for (int s = 128; s > 0; s >>= 1) {
        if (t < s) red[t] = fmaxf(red[t], red[t + s]);
        __syncthreads();
    }
    const float m = red[0];
    __syncthreads();

    float e0 = __expf(v0 - m), e1 = __expf(v1 - m), e2 = __expf(v2 - m);
    red[t] = e0 + e1 + e2;
    __syncthreads();
#pragma unroll
    for (int s = 128; s > 0; s >>= 1) {
        if (t < s) red[t] += red[t + s];
        __syncthreads();
    }
    const float inv = 1.0f / red[0];
    e0 *= inv; e1 *= inv; e2 *= inv;
    float* q = out + row * 768;
    q[t] = e0; q[t + 256] = e1; q[t + 512] = e2;
    if (outb) {
        __nv_bfloat16* qb = outb + row * 768;
        qb[t] = __float2bfloat16_rn(e0);
        qb[t + 256] = __float2bfloat16_rn(e1);
        qb[t + 512] = __float2bfloat16_rn(e2);
    }
}

// ---------------------------------------------------------------------------
// Fused gate conv + Smix (fast-math MUFU version).
// ---------------------------------------------------------------------------
__global__ __launch_bounds__(256) void mix_kernel(
    const float* __restrict__ S1, const float* __restrict__ S2,
    const float* __restrict__ Cr, const float* __restrict__ Cl,
    float* __restrict__ Smix,
    const float* __restrict__ w1, const float* __restrict__ b1,
    const float* __restrict__ w2, const float* __restrict__ b2)
{
    __shared__ float T1[64][65];
    __shared__ float T2[64][65];
    __shared__ float sw1[96], sb1[16], sw2[64], sb2[4];

    const int tid = threadIdx.x;
    if (tid < 96) sw1[tid] = w1[tid];
    if (tid < 16) sb1[tid] = b1[tid];
    if (tid < 64) sw2[tid] = w2[tid];
    if (tid < 4)  sb2[tid] = b2[tid];

    const size_t base = (size_t)blockIdx.z * 768 * 768;
    const int nt = blockIdx.y * 64, mt = blockIdx.x * 64;

#pragma unroll
    for (int u = 0; u < 4; u++) {
        int f = tid + u * 256;
        int r = f >> 4, c4 = (f & 15) * 4;
        size_t off = base + (size_t)(mt + r) * 768 + nt + c4;
        float4 a = *(const float4*)(S1 + off);
        T1[c4 + 0][r] = a.x; T1[c4 + 1][r] = a.y; T1[c4 + 2][r] = a.z; T1[c4 + 3][r] = a.w;
        float4 c = *(const float4*)(S2 + off);
        T2[c4 + 0][r] = c.x; T2[c4 + 1][r] = c.y; T2[c4 + 2][r] = c.z; T2[c4 + 3][r] = c.w;
    }
    __syncthreads();

#pragma unroll 1
    for (int u = 0; u < 16; u++) {
        int e = tid + u * 256;
        int i = e >> 6, j = e & 63;
        size_t idx = base + (size_t)(nt + i) * 768 + mt + j;
        float s1 = S1[idx], s2 = S2[idx];
        float s1t = T1[i][j], s2t = T2[i][j];
        float cr = Cr[idx], cl = Cl[idx];
        float feat[6] = {s1, s2, s1t, s2t, cr, cl};

        float g[4] = {sb2[0], sb2[1], sb2[2], sb2[3]};
#pragma unroll
        for (int o = 0; o < 16; o++) {
            float hv = sb1[o];
#pragma unroll
            for (int c = 0; c < 6; c++) hv = fmaf(feat[c], sw1[o * 6 + c], hv);
            float th = tanh_apx(0.7978845608028654f * (hv + 0.044715f * hv * hv * hv));
            float hid = 0.5f * hv * (1.0f + th);
#pragma unroll
            for (int q = 0; q < 4; q++) g[q] = fmaf(hid, sw2[q * 16 + o], g[q]);
        }
        float gA = sigmoid_f(g[0]);
        float gO = sigmoid_f(g[1]);
        float gN = sigmoid_f(g[2]);
        float gC = sigmoid_f(g[3]);
        float mx = fmaxf(s1, s2), mn = fminf(s1, s2);
        float lae = mx + __logf(1.0f + __expf(mn - mx));
        Smix[idx] = s1 + gA * s2 + gO * (lae - s1) - gN * (0.5f * s2) + gC * cr;
    }
}

// ---------------------------------------------------------------------------
extern "C" void kernel_launch(void* const* d_in, const int* in_sizes, int n_in,
                              void* d_out, int out_size)
{
    const float* x        = (const float*)d_in[0];
    const float* qkv1_w   = (const float*)d_in[1];
    const float* qkv2_w   = (const float*)d_in[2];
    const float* proj_w   = (const float*)d_in[3];
    const float* conv1_w  = (const float*)d_in[4];
    const float* conv1_b  = (const float*)d_in[5];
    const float* conv2_w  = (const float*)d_in[6];
    const float* conv2_b  = (const float*)d_in[7];
    const float* chlogit  = (const float*)d_in[8];
    float* out = (float*)d_out;

    float *p_raw1, *p_raw2, *p_kT1, *p_kT2, *p_S1, *p_S2, *p_A1, *p_A2;
    float *p_Cr, *p_Cl, *p_Smix, *p_y2, *p_y;
    __nv_bfloat16 *p_A1b, *p_A2b, *p_A1tb, *p_A2tb;
    cudaGetSymbolAddress((void**)&p_raw1, g_raw1);
    cudaGetSymbolAddress((void**)&p_raw2, g_raw2);
    cudaGetSymbolAddress((void**)&p_kT1, g_kT1);
    cudaGetSymbolAddress((void**)&p_kT2, g_kT2);
    cudaGetSymbolAddress((void**)&p_S1, g_S1);
    cudaGetSymbolAddress((void**)&p_S2, g_S2);
    cudaGetSymbolAddress((void**)&p_A1, g_A1);
    cudaGetSymbolAddress((void**)&p_A2, g_A2);
    cudaGetSymbolAddress((void**)&p_Cr, g_Cr);
    cudaGetSymbolAddress((void**)&p_Cl, g_Cl);
    cudaGetSymbolAddress((void**)&p_Smix, g_Smix);
    cudaGetSymbolAddress((void**)&p_y2, g_y2);
    cudaGetSymbolAddress((void**)&p_y, g_y);
    cudaGetSymbolAddress((void**)&p_A1b, g_A1b);
    cudaGetSymbolAddress((void**)&p_A2b, g_A2b);
    cudaGetSymbolAddress((void**)&p_A1tb, g_A1tb);
    cudaGetSymbolAddress((void**)&p_A2tb, g_A2tb);

    cudaFuncSetAttribute(hmma_logC,
                         cudaFuncAttributeMaxDynamicSharedMemorySize, HSM_TOTAL);

    const size_t SB = 768 * 768;
    const size_t RB = 768 * 1536;
    const size_t VB = 768 * 64;
    const size_t YB = 768 * 512;

    // 1) both QKV projections in one launch (z=2, 288 CTAs)
    sgemm128<<<dim3(12, 12, 2), 256>>>(x, qkv1_w, p_raw1,
                                       x, qkv2_w, p_raw2,
                                       512, 0, 0, 1536, 0, 0, 1536, 0, 0,
                                       512, 1.0f, 1);

    // 2) both K transposes in one launch
    transposeK<<<dim3(24, 2, 32), dim3(32, 8)>>>(p_raw1, p_kT1, p_raw2, p_kT2);

    // 3) S1 & S2 in one launch (z=32, 1152 CTAs)
    sgemm128<<<dim3(6, 6, 32), 256>>>(p_raw1, p_kT1, p_S1,
                                      p_raw2, p_kT2, p_S2,
                                      1536, RB, 64, 768, 8 * VB, VB,
                                      768, 8 * SB, SB,
                                      64, 0.125f, 16);

    // 4) A1/A2 softmax (+ bf16 copies) — merged
    softmax768<<<24576, 256>>>(p_S1, p_A1, p_A1b, p_S2, p_A2, p_A2b);

    // 4b) transposed bf16 copies — merged
    transpose_cvt<<<dim3(24, 24, 32), dim3(32, 8)>>>(p_A1, p_A1tb, p_A2, p_A2tb);

    // 5) Cr & Cl (+ raw C_right into g_A1, A1 fp32 is dead from here)
    hmma_logC<<<dim3(6, 6, 32), 256, HSM_TOTAL>>>(p_A1b, p_A2tb, p_A2b, p_A1tb,
                                                  p_Cr, p_Cl, p_A1);

    // 6) fused gate conv + Smix
    mix_kernel<<<dim3(12, 12, 16), 256>>>(p_S1, p_S2, p_Cr, p_Cl, p_Smix,
                                          conv1_w, conv1_b, conv2_w, conv2_b);

    // 7) A = softmax(Smix) in place
    softmax768<<<12288, 256>>>(p_Smix, p_Smix, nullptr,
                               p_Smix, p_Smix, nullptr);

    // 8) y_base = A @ v1  ∥  y_chain = Craw @ v2  (one launch, 384 CTAs)
    sgemm64d<<<dim3(1, 12, 32), 256>>>(p_Smix, p_raw1 + 1024, p_y,
                                       p_A1,   p_raw2 + 1024, p_y2,
                                       768, 8 * SB, SB,
                                       1536, RB, 64,
                                       512, YB, 64,
                                       768, 16);

    // 9) out = (y_base + sigmoid(chain_logit) * y_chain) @ proj_w
    proj_kernel<<<dim3(8, 24), 256>>>(p_y, p_y2, proj_w, out, chlogit);
}